// round 8
// baseline (speedup 1.0000x reference)
#include <cuda_runtime.h>
#include <cuda_bf16.h>
#include <cuda_fp16.h>
#include <cstdint>

#define NNODES 100000
#define NEDGES 3200000

// ------------------------- device scratch (no allocs) -----------------------
__device__ __align__(16) __half g_ky[(size_t)NNODES * 64];
__device__ __align__(16) float  g_sums[(size_t)NNODES * 64];
__device__ float g_cnt[NNODES];
// frag-linear W2: uint32 idx = ((((ki*4+c)*4+ks)*32+nt)*32+lane)*4 + s*2 + r
// consumed as uint4 {bh0,bh1,bl0,bl1} per (ki,c,ks,nt,lane). 512KB total.
__device__ __align__(16) uint32_t g_Bf[131072];

#define SWZ(o) ((o) ^ (((o) >> 3) & 0x70))

__device__ __forceinline__ uint32_t smem_u32(const void* p) {
    uint32_t a;
    asm("{ .reg .u64 t; cvta.to.shared.u64 t, %1; cvt.u32.u64 %0, t; }"
        : "=r"(a) : "l"(p));
    return a;
}
__device__ __forceinline__ void ldsm_x4(uint32_t* r, uint32_t a) {
    asm volatile("ldmatrix.sync.aligned.m8n8.x4.shared.b16 {%0,%1,%2,%3}, [%4];"
                 : "=r"(r[0]), "=r"(r[1]), "=r"(r[2]), "=r"(r[3]) : "r"(a));
}
__device__ __forceinline__ void mma16816(float* d, const uint32_t* a, const uint32_t* b) {
    asm volatile("mma.sync.aligned.m16n8k16.row.col.f32.bf16.bf16.f32 "
                 "{%0,%1,%2,%3}, {%4,%5,%6,%7}, {%8,%9}, {%0,%1,%2,%3};"
                 : "+f"(d[0]), "+f"(d[1]), "+f"(d[2]), "+f"(d[3])
                 : "r"(a[0]), "r"(a[1]), "r"(a[2]), "r"(a[3]),
                   "r"(b[0]), "r"(b[1]));
}

// ---------------- prep (W2 -> frag-linear bf16 split) + zero accumulators ----
__global__ void __launch_bounds__(256)
prep_zero(const float* __restrict__ W2a, const float* __restrict__ W2b) {
    int id = blockIdx.x * blockDim.x + threadIdx.x;   // 1.6M threads
    if (id < NNODES * 16)
        ((float4*)g_sums)[id] = make_float4(0.f, 0.f, 0.f, 0.f);
    if (id < NNODES)
        g_cnt[id] = 0.f;
    if (id < 131072) {
        int r    = id & 1;
        int s    = (id >> 1) & 1;
        int lane = (id >> 2) & 31;
        int nt   = (id >> 7) & 31;
        int ks   = (id >> 12) & 3;
        int c    = (id >> 14) & 3;
        int ki   = (id >> 16) & 1;
        const float* W2 = ki ? W2b : W2a;
        int m   = ks * 16 + 2 * (lane & 3) + r * 8;      // k-dim (MLP neuron)
        int col = c * 256 + nt * 8 + (lane >> 2);        // output col within W2 row
        float w0 = W2[m * 1024 + col];
        float w1 = W2[(m + 1) * 1024 + col];
        __nv_bfloat16 h0 = __float2bfloat16(w0);
        __nv_bfloat16 h1 = __float2bfloat16(w1);
        uint32_t v;
        if (s == 0) {
            v = ((uint32_t)__bfloat16_as_ushort(h1) << 16) | __bfloat16_as_ushort(h0);
        } else {
            __nv_bfloat16 l0 = __float2bfloat16(w0 - __bfloat162float(h0));
            __nv_bfloat16 l1 = __float2bfloat16(w1 - __bfloat162float(h1));
            v = ((uint32_t)__bfloat16_as_ushort(l1) << 16) | __bfloat16_as_ushort(l0);
        }
        g_Bf[id] = v;
    }
}

// ------------------------- fused HMMA pass ----------------------------------
// 64 nodes/CTA, 8 warps, 2 CTAs/SM. Warp: m-tile rb=wid&3 (16 rows),
// j-half par=wid>>2 (owns all 16 k for j in [8par,8par+8)) -> warp-local
// epilogue, no syncs in channel loop. B frags LDG'd from frag-linear global.
// D = Ah@Bh^T + Ah@Bl^T + Al@Bh^T (fp32 acc);
// y[n,c*16+j] = sum_k x[n,c,k]*(D+b2). Pass1 writes fp16 ky; pass2 ys+mix.
template<bool DIVCNT, bool DOMIX>
__global__ void __launch_bounds__(256, 2)
mma_fused(const float* __restrict__ xin, const float* __restrict__ ea,
          const float* __restrict__ W1,  const float* __restrict__ b1,
          const float* __restrict__ b2,  const float* __restrict__ cnt,
          const float* __restrict__ mixW, const float* __restrict__ mixb,
          float* __restrict__ fout, __half* __restrict__ hout, int ki)
{
    extern __shared__ char smem[];                 // AH 8192 | AL 8192 | [ys | mixW]
    const uint32_t smb = smem_u32(smem);
    float* ys  = (float*)(smem + 16384);           // 64 x 68 floats
    float* mWs = (float*)(smem + 16384 + 17408);
    const int tid = threadIdx.x, wid = tid >> 5, lid = tid & 31;
    const int nb0 = blockIdx.x * 64;

    // ---- h = relu(ea@W1+b1), bf16 split into A tiles. thread: node tid>>2 ----
    {
        int n = tid >> 2, gn = nb0 + n, mb = (tid & 3) * 16;
        float e0 = 0.f, e1 = 0.f, e2 = 0.f;
        if (gn < NNODES) { e0 = ea[gn*3]; e1 = ea[gn*3+1]; e2 = ea[gn*3+2]; }
        #pragma unroll
        for (int q = 0; q < 16; q++) {
            int m = mb + q;
            float h = 0.f;
            if (gn < NNODES)
                h = fmaxf(fmaf(e2, W1[128+m], fmaf(e1, W1[64+m], fmaf(e0, W1[m], b1[m]))), 0.f);
            __nv_bfloat16 hi = __float2bfloat16(h);
            __nv_bfloat16 lo = __float2bfloat16(h - __bfloat162float(hi));
            uint32_t off = SWZ((uint32_t)(n * 128 + m * 2));
            *(__nv_bfloat16*)(smem + off) = hi;
            *(__nv_bfloat16*)(smem + 8192 + off) = lo;
        }
    }
    if (DOMIX) {
        for (int i = tid; i < 1024; i += 256)
            ((float4*)mWs)[i] = ((const float4*)mixW)[i];
    }
    __syncthreads();

    const int rb = wid & 3, par = wid >> 2;
    const uint32_t arow = (uint32_t)(rb * 16 + (lid & 7) + ((lid >> 3) & 1) * 8);
    const uint32_t acol = (uint32_t)(((lid >> 4) & 1) * 8);
    const int jlo = (lid & 3) * 2;

    int rowg[2]; float rcs[2];
    #pragma unroll
    for (int g = 0; g < 2; g++) {
        rowg[g] = rb * 16 + g * 8 + (lid >> 2);
        int gn = nb0 + rowg[g];
        float r = 1.f;
        if (DIVCNT && gn < NNODES) r = 1.f / fmaxf(cnt[gn], 1.f);
        rcs[g] = r;
    }

    for (int c = 0; c < 4; c++) {
        const uint4* Bq = (const uint4*)g_Bf + (size_t)((ki * 4 + c) * 4) * 1024;
        float y[2][2];
        y[0][0] = y[0][1] = y[1][0] = y[1][1] = 0.f;

        #pragma unroll
        for (int qh = 0; qh < 2; qh++) {
            float acc[8][4];
            #pragma unroll
            for (int qq = 0; qq < 8; qq++)
                #pragma unroll
                for (int e = 0; e < 4; e++) acc[qq][e] = 0.f;

            #pragma unroll
            for (int ks = 0; ks < 4; ks++) {
                uint32_t ahf[4], alf[4];
                uint32_t off = arow * 128u + (ks * 16 + acol) * 2u;
                ldsm_x4(ahf, smb + SWZ(off));
                ldsm_x4(alf, smb + 8192u + SWZ(off));
                #pragma unroll
                for (int qq = 0; qq < 8; qq++) {
                    int nt = (qh * 8 + qq) * 2 + par;     // n-tile = 16k + 8par
                    uint4 bq = Bq[(ks * 32 + nt) * 32 + lid];
                    uint32_t bh[2] = {bq.x, bq.y};
                    uint32_t bl[2] = {bq.z, bq.w};
                    mma16816(acc[qq], ahf, bh);
                    mma16816(acc[qq], ahf, bl);
                    mma16816(acc[qq], alf, bh);
                }
            }

            // epilogue: contract with x (k = qh*8+qq), add b2
            float b2v[8][2];
            #pragma unroll
            for (int qq = 0; qq < 8; qq++) {
                int t0 = c * 256 + (qh * 8 + qq) * 16 + 8 * par + jlo;
                b2v[qq][0] = b2[t0];
                b2v[qq][1] = b2[t0 + 1];
            }
            #pragma unroll
            for (int g = 0; g < 2; g++) {
                int gn = nb0 + rowg[g];
                float xk[8];
                #pragma unroll
                for (int q = 0; q < 8; q++) xk[q] = 0.f;
                if (gn < NNODES) {
                    float4 a = *(const float4*)(xin + (size_t)gn*64 + c*16 + qh*8);
                    float4 b = *(const float4*)(xin + (size_t)gn*64 + c*16 + qh*8 + 4);
                    xk[0]=a.x*rcs[g]; xk[1]=a.y*rcs[g]; xk[2]=a.z*rcs[g]; xk[3]=a.w*rcs[g];
                    xk[4]=b.x*rcs[g]; xk[5]=b.y*rcs[g]; xk[6]=b.z*rcs[g]; xk[7]=b.w*rcs[g];
                }
                #pragma unroll
                for (int qq = 0; qq < 8; qq++) {
                    y[g][0] = fmaf(xk[qq], acc[qq][g*2]     + b2v[qq][0], y[g][0]);
                    y[g][1] = fmaf(xk[qq], acc[qq][g*2 + 1] + b2v[qq][1], y[g][1]);
                }
            }
        }

        // store channel result (warp-exclusive, race-free)
        if (!DOMIX) {
            #pragma unroll
            for (int g = 0; g < 2; g++) {
                int gn = nb0 + rowg[g];
                if (gn < NNODES)
                    *(__half2*)(hout + (size_t)gn*64 + c*16 + 8*par + jlo) =
                        __floats2half2_rn(y[g][0], y[g][1]);
            }
        } else {
            #pragma unroll
            for (int g = 0; g < 2; g++) {
                float* yp = ys + rowg[g] * 68 + c * 16 + 8 * par + jlo;
                yp[0] = y[g][0]; yp[1] = y[g][1];
            }
        }
    }

    // ---- mix linear (pass 2): out = ys @ mixW^T + mixb ----
    if (DOMIX) {
        __syncthreads();
        const int n = tid >> 2, ob = (tid & 3) * 16;
        const int gn = nb0 + n;
        const float4* ys4 = (const float4*)(smem + 16384) + n * 17;
        const float4* mw4 = (const float4*)mWs;
        float a2[16];
        #pragma unroll
        for (int o = 0; o < 16; o++) a2[o] = 0.f;
        #pragma unroll 4
        for (int v4 = 0; v4 < 16; v4++) {
            float4 yv = ys4[v4];
            #pragma unroll
            for (int o = 0; o < 16; o++) {
                float4 w4 = mw4[(ob + o) * 16 + v4];
                a2[o] = fmaf(yv.x, w4.x, a2[o]);
                a2[o] = fmaf(yv.y, w4.y, a2[o]);
                a2[o] = fmaf(yv.z, w4.z, a2[o]);
                a2[o] = fmaf(yv.w, w4.w, a2[o]);
            }
        }
        if (gn < NNODES) {
            #pragma unroll
            for (int o = 0; o < 16; o++)
                fout[(size_t)gn * 64 + ob + o] = a2[o] + mixb[ob + o];
        }
    }
}

// ------------------------- scatter-sum over edges (ILP x4, fp16 gather) -----
__global__ void __launch_bounds__(256)
scatter_kernel(const int* __restrict__ ei) {
    const int QE = NEDGES / 4;                       // 800000
    int t = blockIdx.x * blockDim.x + threadIdx.x;
    if (t >= QE * 16) return;
    int e0 = t >> 4, q = t & 15;
    int dst[4], src[4];
    #pragma unroll
    for (int i = 0; i < 4; i++) {
        int e = e0 + i * QE;
        dst[i] = ei[e];
        src[i] = ei[NEDGES + e];
    }
    float4 v[4];
    #pragma unroll
    for (int i = 0; i < 4; i++) {
        uint2 u = *(const uint2*)((const __half*)g_ky + (size_t)src[i] * 64 + q * 4);
        float2 f0 = __half22float2(*(__half2*)&u.x);
        float2 f1 = __half22float2(*(__half2*)&u.y);
        v[i] = make_float4(f0.x, f0.y, f1.x, f1.y);
    }
    #pragma unroll
    for (int i = 0; i < 4; i++)
        atomicAdd(&((float4*)g_sums)[(size_t)dst[i] * 16 + q], v[i]);
    if (q == 0) {
        #pragma unroll
        for (int i = 0; i < 4; i++)
            atomicAdd(&g_cnt[dst[i]], 1.0f);
    }
}

// -----------------------------------------------------------------------------
extern "C" void kernel_launch(void* const* d_in, const int* in_sizes, int n_in,
                              void* d_out, int out_size)
{
    const float* x    = (const float*)d_in[0];
    const float* ea   = (const float*)d_in[1];
    const int*   ei   = (const int*)  d_in[2];
    const float* k1W1 = (const float*)d_in[3];
    const float* k1b1 = (const float*)d_in[4];
    const float* k1W2 = (const float*)d_in[5];
    const float* k1b2 = (const float*)d_in[6];
    const float* k2W1 = (const float*)d_in[7];
    const float* k2b1 = (const float*)d_in[8];
    const float* k2W2 = (const float*)d_in[9];
    const float* k2b2 = (const float*)d_in[10];
    const float* mixW = (const float*)d_in[11];
    const float* mixb = (const float*)d_in[12];
    float* out = (float*)d_out;

    __half* ky_p = nullptr; float *sums_p = nullptr, *cnt_p = nullptr;
    cudaGetSymbolAddress((void**)&ky_p,   g_ky);
    cudaGetSymbolAddress((void**)&sums_p, g_sums);
    cudaGetSymbolAddress((void**)&cnt_p,  g_cnt);

    const int SM1 = 16384;                    // AH + AL
    const int SM2 = 16384 + 17408 + 16384;    // + ys + mixW
    cudaFuncSetAttribute((const void*)mma_fused<false, false>,
                         cudaFuncAttributeMaxDynamicSharedMemorySize, SM1);
    cudaFuncSetAttribute((const void*)mma_fused<true, true>,
                         cudaFuncAttributeMaxDynamicSharedMemorySize, SM2);

    const int grid = (NNODES + 63) / 64;      // 1563

    prep_zero<<<(NNODES * 16 + 255) / 256, 256>>>(k1W2, k2W2);

    mma_fused<false, false><<<grid, 256, SM1>>>(
        x, ea, k1W1, k1b1, k1b2, nullptr, nullptr, nullptr, nullptr, ky_p, 0);

    scatter_kernel<<<(NEDGES / 4 * 16 + 255) / 256, 256>>>(ei);

    mma_fused<true, true><<<grid, 256, SM2>>>(
        sums_p, ea, k2W1, k2b1, k2b2, cnt_p, mixW, mixb, out, nullptr, 1);
}

// round 9
// speedup vs baseline: 1.2118x; 1.2118x over previous
#include <cuda_runtime.h>
#include <cuda_bf16.h>
#include <cuda_fp16.h>
#include <cstdint>

#define NNODES 100000
#define NEDGES 3200000

// ------------------------- device scratch (no allocs) -----------------------
__device__ __align__(16) __half g_ky[(size_t)NNODES * 64];
__device__ __align__(16) float  g_sums[(size_t)NNODES * 64];
__device__ __align__(16) float  g_v[(size_t)NNODES * 64];
__device__ float g_cnt[NNODES];
// pre-split, transposed (t-major), SW128-swizzled W2 tiles:
// [ki][c] -> 256 rows (t) x 64 cols (m) bf16, 128B/row, 32KB per tile
__device__ __align__(16) __nv_bfloat16 g_Bh[2 * 4 * 256 * 64];
__device__ __align__(16) __nv_bfloat16 g_Bl[2 * 4 * 256 * 64];

#define SWZ(o) ((o) ^ (((o) >> 3) & 0x70))

__device__ __forceinline__ uint32_t smem_u32(const void* p) {
    uint32_t a;
    asm("{ .reg .u64 t; cvta.to.shared.u64 t, %1; cvt.u32.u64 %0, t; }"
        : "=r"(a) : "l"(p));
    return a;
}
__device__ __forceinline__ void ldsm_x4(uint32_t* r, uint32_t a) {
    asm volatile("ldmatrix.sync.aligned.m8n8.x4.shared.b16 {%0,%1,%2,%3}, [%4];"
                 : "=r"(r[0]), "=r"(r[1]), "=r"(r[2]), "=r"(r[3]) : "r"(a));
}
__device__ __forceinline__ void mma16816(float* d, const uint32_t* a, const uint32_t* b) {
    asm volatile("mma.sync.aligned.m16n8k16.row.col.f32.bf16.bf16.f32 "
                 "{%0,%1,%2,%3}, {%4,%5,%6,%7}, {%8,%9}, {%0,%1,%2,%3};"
                 : "+f"(d[0]), "+f"(d[1]), "+f"(d[2]), "+f"(d[3])
                 : "r"(a[0]), "r"(a[1]), "r"(a[2]), "r"(a[3]),
                   "r"(b[0]), "r"(b[1]));
}
__device__ __forceinline__ void cpasync16(uint32_t dst, const void* src) {
    asm volatile("cp.async.ca.shared.global [%0], [%1], 16;" :: "r"(dst), "l"(src));
}
#define CP_COMMIT() asm volatile("cp.async.commit_group;" ::: "memory")
#define CP_WAIT0()  asm volatile("cp.async.wait_group 0;" ::: "memory")

// SMEM layout (bytes): AH 8K | AL 8K | B (Bh 32K + Bl 32K)
#define SM_AH    0
#define SM_AL    8192
#define SM_B     16384
#define SM_TOTAL 81920

// ---------------- prep (W2 -> split/transposed/swizzled tiles) + zero -------
__global__ void __launch_bounds__(256)
prep_zero(const float* __restrict__ W2a, const float* __restrict__ W2b) {
    int id = blockIdx.x * blockDim.x + threadIdx.x;   // 1.6M threads
    if (id < NNODES * 16)
        ((float4*)g_sums)[id] = make_float4(0.f, 0.f, 0.f, 0.f);
    if (id < NNODES)
        g_cnt[id] = 0.f;
    if (id < 131072) {
        int ki = id >> 16;
        int r  = id & 65535;
        int c  = r >> 14;
        int t  = (r >> 6) & 255;
        int m  = r & 63;
        const float* W2 = ki ? W2b : W2a;
        float w = W2[m * 1024 + c * 256 + t];
        __nv_bfloat16 hi = __float2bfloat16(w);
        __nv_bfloat16 lo = __float2bfloat16(w - __bfloat162float(hi));
        uint32_t off = SWZ((uint32_t)(t * 128 + m * 2));
        size_t tb = (size_t)(ki * 4 + c) * 32768;
        *(__nv_bfloat16*)((char*)g_Bh + tb + off) = hi;
        *(__nv_bfloat16*)((char*)g_Bl + tb + off) = lo;
    }
}

// ------------------------- fused HMMA pass ----------------------------------
// 64 nodes/CTA, 8 warps, 2 CTAs/SM. Warp: m-tile rb=wid&3 (16 rows),
// j-half par=wid>>2 (owns all 16 k for its 8 j's) -> warp-local epilogue.
// B staged in smem (cp.async), b-frags via ldmatrix x4 pairing (nt, nt+2).
// D = Ah@Bh^T + Ah@Bl^T + Al@Bh^T (fp32 acc);
// y[n,c*16+j] = sum_k x[n,c,k]*(D+b2), x scaled 1/max(cnt,1) if DIVCNT.
template<bool DIVCNT, bool STOREHALF>
__global__ void __launch_bounds__(256, 2)
mma_fused(const float* __restrict__ xin, const float* __restrict__ ea,
          const float* __restrict__ W1,  const float* __restrict__ b1,
          const float* __restrict__ b2,  const float* __restrict__ cnt,
          float* __restrict__ fout, __half* __restrict__ hout, int ki)
{
    extern __shared__ char smem[];
    const uint32_t smb = smem_u32(smem);
    const int tid = threadIdx.x, wid = tid >> 5, lid = tid & 31;
    const int nb0 = blockIdx.x * 64;

    // ---- h = relu(ea@W1+b1), bf16 split into A tiles. thread: node tid>>2 ----
    {
        int n = tid >> 2, gn = nb0 + n, mb = (tid & 3) * 16;
        float e0 = 0.f, e1 = 0.f, e2 = 0.f;
        if (gn < NNODES) { e0 = ea[gn*3]; e1 = ea[gn*3+1]; e2 = ea[gn*3+2]; }
        #pragma unroll
        for (int q = 0; q < 16; q++) {
            int m = mb + q;
            float h = 0.f;
            if (gn < NNODES)
                h = fmaxf(fmaf(e2, W1[128+m], fmaf(e1, W1[64+m], fmaf(e0, W1[m], b1[m]))), 0.f);
            __nv_bfloat16 hi = __float2bfloat16(h);
            __nv_bfloat16 lo = __float2bfloat16(h - __bfloat162float(hi));
            uint32_t off = SWZ((uint32_t)(n * 128 + m * 2));
            *(__nv_bfloat16*)(smem + SM_AH + off) = hi;
            *(__nv_bfloat16*)(smem + SM_AL + off) = lo;
        }
    }

    const int rb = wid & 3, par = wid >> 2;
    const uint32_t arow = (uint32_t)(rb * 16 + (lid & 7) + ((lid >> 3) & 1) * 8);
    const uint32_t acol = (uint32_t)(((lid >> 4) & 1) * 8);
    const int jlo = (lid & 3) * 2;
    // per-lane B x4 addressing: lanes 16-31 take matrix pair nt+2
    const int bsel  = ((lid >> 4) & 1) * 2;
    const int brow8 = lid & 7;
    const int bkoff = ((lid >> 3) & 1) * 8;

    int rowg[2]; float rcs[2];
    #pragma unroll
    for (int g = 0; g < 2; g++) {
        rowg[g] = rb * 16 + g * 8 + (lid >> 2);
        int gn = nb0 + rowg[g];
        float r = 1.f;
        if (DIVCNT && gn < NNODES) r = 1.f / fmaxf(cnt[gn], 1.f);
        rcs[g] = r;
    }

    for (int c = 0; c < 4; c++) {
        // stage B tiles (pre-swizzled in global): 64KB via cp.async
        {
            const char* sh = (const char*)g_Bh + (size_t)(ki * 4 + c) * 32768;
            const char* sl = (const char*)g_Bl + (size_t)(ki * 4 + c) * 32768;
            #pragma unroll
            for (int i = 0; i < 8; i++) {
                uint32_t o = (uint32_t)(tid * 16 + i * 4096);
                cpasync16(smb + SM_B + o, sh + o);
                cpasync16(smb + SM_B + 32768u + o, sl + o);
            }
        }
        CP_COMMIT(); CP_WAIT0();
        __syncthreads();   // B staged (and A tiles on first iter)

        float y[2][2];
        y[0][0] = y[0][1] = y[1][0] = y[1][1] = 0.f;

        #pragma unroll
        for (int qh = 0; qh < 2; qh++) {
            float acc[8][4];
            #pragma unroll
            for (int qq = 0; qq < 8; qq++)
                #pragma unroll
                for (int e = 0; e < 4; e++) acc[qq][e] = 0.f;

            #pragma unroll
            for (int ks = 0; ks < 4; ks++) {
                uint32_t ahf[4], alf[4];
                uint32_t aoff = arow * 128u + (ks * 16 + acol) * 2u;
                ldsm_x4(ahf, smb + SM_AH + SWZ(aoff));
                ldsm_x4(alf, smb + SM_AL + SWZ(aoff));
                #pragma unroll
                for (int qp = 0; qp < 4; qp++) {
                    int k0 = qh * 8 + qp * 2;
                    int nts = k0 * 2 + par + bsel;       // this lane's matrix pair
                    uint32_t boff = (uint32_t)(nts * 8 + brow8) * 128u
                                  + (uint32_t)(ks * 16 + bkoff) * 2u;
                    uint32_t bh4[4], bl4[4];
                    ldsm_x4(bh4, smb + SM_B + SWZ(boff));
                    ldsm_x4(bl4, smb + SM_B + 32768u + SWZ(boff));
                    mma16816(acc[qp*2],     ahf, bh4);
                    mma16816(acc[qp*2],     ahf, bl4);
                    mma16816(acc[qp*2],     alf, bh4);
                    mma16816(acc[qp*2 + 1], ahf, bh4 + 2);
                    mma16816(acc[qp*2 + 1], ahf, bl4 + 2);
                    mma16816(acc[qp*2 + 1], alf, bh4 + 2);
                }
            }

            // epilogue: contract with x (k = qh*8+qq), add b2
            float b2v[8][2];
            #pragma unroll
            for (int qq = 0; qq < 8; qq++) {
                int t0 = c * 256 + (qh * 8 + qq) * 16 + 8 * par + jlo;
                b2v[qq][0] = b2[t0];
                b2v[qq][1] = b2[t0 + 1];
            }
            #pragma unroll
            for (int g = 0; g < 2; g++) {
                int gn = nb0 + rowg[g];
                float xk[8];
                #pragma unroll
                for (int q = 0; q < 8; q++) xk[q] = 0.f;
                if (gn < NNODES) {
                    float4 a = *(const float4*)(xin + (size_t)gn*64 + c*16 + qh*8);
                    float4 b = *(const float4*)(xin + (size_t)gn*64 + c*16 + qh*8 + 4);
                    xk[0]=a.x*rcs[g]; xk[1]=a.y*rcs[g]; xk[2]=a.z*rcs[g]; xk[3]=a.w*rcs[g];
                    xk[4]=b.x*rcs[g]; xk[5]=b.y*rcs[g]; xk[6]=b.z*rcs[g]; xk[7]=b.w*rcs[g];
                }
                #pragma unroll
                for (int qq = 0; qq < 8; qq++) {
                    y[g][0] = fmaf(xk[qq], acc[qq][g*2]     + b2v[qq][0], y[g][0]);
                    y[g][1] = fmaf(xk[qq], acc[qq][g*2 + 1] + b2v[qq][1], y[g][1]);
                }
            }
        }

        // store channel result (warp-exclusive, race-free)
        #pragma unroll
        for (int g = 0; g < 2; g++) {
            int gn = nb0 + rowg[g];
            if (gn < NNODES) {
                if (STOREHALF)
                    *(__half2*)(hout + (size_t)gn*64 + c*16 + 8*par + jlo) =
                        __floats2half2_rn(y[g][0], y[g][1]);
                else
                    *(float2*)(fout + (size_t)gn*64 + c*16 + 8*par + jlo) =
                        make_float2(y[g][0], y[g][1]);
            }
        }

        __syncthreads();   // all warps done with B buffer before restage
    }
}

// ------------------------- scatter-sum over edges (ILP x4, fp16 gather) -----
__global__ void __launch_bounds__(256)
scatter_kernel(const int* __restrict__ ei) {
    const int QE = NEDGES / 4;                       // 800000
    int t = blockIdx.x * blockDim.x + threadIdx.x;
    if (t >= QE * 16) return;
    int e0 = t >> 4, q = t & 15;
    int dst[4], src[4];
    #pragma unroll
    for (int i = 0; i < 4; i++) {
        int e = e0 + i * QE;
        dst[i] = ei[e];
        src[i] = ei[NEDGES + e];
    }
    float4 v[4];
    #pragma unroll
    for (int i = 0; i < 4; i++) {
        uint2 u = *(const uint2*)((const __half*)g_ky + (size_t)src[i] * 64 + q * 4);
        float2 f0 = __half22float2(*(__half2*)&u.x);
        float2 f1 = __half22float2(*(__half2*)&u.y);
        v[i] = make_float4(f0.x, f0.y, f1.x, f1.y);
    }
    #pragma unroll
    for (int i = 0; i < 4; i++)
        atomicAdd(&((float4*)g_sums)[(size_t)dst[i] * 16 + q], v[i]);
    if (q == 0) {
        #pragma unroll
        for (int i = 0; i < 4; i++)
            atomicAdd(&g_cnt[dst[i]], 1.0f);
    }
}

// ------------------------- mix linear: out = v @ mixW^T + mixb --------------
__global__ void __launch_bounds__(256)
mix_kernel(const float* __restrict__ mixW, const float* __restrict__ mixb,
           float* __restrict__ out)
{
    __shared__ float mWs[4096];
    int tid = threadIdx.x;
    for (int i = tid; i < 1024; i += 256)
        ((float4*)mWs)[i] = ((const float4*)mixW)[i];
    __syncthreads();

    int n = blockIdx.x * 128 + (tid >> 1);
    int ob = (tid & 1) * 32;
    if (n >= NNODES) return;
    const float4* v4 = (const float4*)(g_v + (size_t)n * 64);
    const float4* mw4 = (const float4*)mWs;
    float a2[32];
    #pragma unroll
    for (int o = 0; o < 32; o++) a2[o] = 0.f;
    #pragma unroll 4
    for (int v = 0; v < 16; v++) {
        float4 yv = v4[v];
        #pragma unroll
        for (int o = 0; o < 32; o++) {
            float4 w4 = mw4[(ob + o) * 16 + v];
            a2[o] = fmaf(yv.x, w4.x, a2[o]);
            a2[o] = fmaf(yv.y, w4.y, a2[o]);
            a2[o] = fmaf(yv.z, w4.z, a2[o]);
            a2[o] = fmaf(yv.w, w4.w, a2[o]);
        }
    }
    #pragma unroll
    for (int o = 0; o < 32; o++)
        out[(size_t)n * 64 + ob + o] = a2[o] + mixb[ob + o];
}

// -----------------------------------------------------------------------------
extern "C" void kernel_launch(void* const* d_in, const int* in_sizes, int n_in,
                              void* d_out, int out_size)
{
    const float* x    = (const float*)d_in[0];
    const float* ea   = (const float*)d_in[1];
    const int*   ei   = (const int*)  d_in[2];
    const float* k1W1 = (const float*)d_in[3];
    const float* k1b1 = (const float*)d_in[4];
    const float* k1W2 = (const float*)d_in[5];
    const float* k1b2 = (const float*)d_in[6];
    const float* k2W1 = (const float*)d_in[7];
    const float* k2b1 = (const float*)d_in[8];
    const float* k2W2 = (const float*)d_in[9];
    const float* k2b2 = (const float*)d_in[10];
    const float* mixW = (const float*)d_in[11];
    const float* mixb = (const float*)d_in[12];
    float* out = (float*)d_out;

    __half* ky_p = nullptr; float *sums_p = nullptr, *cnt_p = nullptr, *v_p = nullptr;
    cudaGetSymbolAddress((void**)&ky_p,   g_ky);
    cudaGetSymbolAddress((void**)&sums_p, g_sums);
    cudaGetSymbolAddress((void**)&cnt_p,  g_cnt);
    cudaGetSymbolAddress((void**)&v_p,    g_v);

    cudaFuncSetAttribute((const void*)mma_fused<false, true>,
                         cudaFuncAttributeMaxDynamicSharedMemorySize, SM_TOTAL);
    cudaFuncSetAttribute((const void*)mma_fused<true, false>,
                         cudaFuncAttributeMaxDynamicSharedMemorySize, SM_TOTAL);

    const int grid = (NNODES + 63) / 64;      // 1563

    prep_zero<<<(NNODES * 16 + 255) / 256, 256>>>(k1W2, k2W2);

    mma_fused<false, true><<<grid, 256, SM_TOTAL>>>(
        x, ea, k1W1, k1b1, k1b2, nullptr, nullptr, ky_p, 0);

    scatter_kernel<<<(NEDGES / 4 * 16 + 255) / 256, 256>>>(ei);

    mma_fused<true, false><<<grid, 256, SM_TOTAL>>>(
        sums_p, ea, k2W1, k2b1, k2b2, cnt_p, v_p, nullptr, 1);

    mix_kernel<<<(NNODES + 127) / 128, 256>>>(mixW, mixb, out);
}